// round 15
// baseline (speedup 1.0000x reference)
#include <cuda_runtime.h>
#include <cstdint>

// ---------------------------------------------------------------------------
// CustomOrientationLoss — FINAL (locked R12 config, best measured 61.44us).
//
//   Z[v] = sum_{(u,v) in E} (x[u]-x[v])*(s[u]-s[v])   [symmetric per edge:
//          computed once, RED-scattered to both endpoints]
//   cos  = <y,Z>/(|y||Z|);  out = { mean(1-|cos|), mean(deg(acos cos)) }
//
// Performance structure (established R4-R13):
//   - edge phase (~52us) sits AT the LTS sector-RMW roofline:
//       6.4M gather sectors + 6.4M RMW sectors, ~(1+2)cyc/slice -> ~58us model.
//     2 RMW sectors/edge is minimal for any scatter formulation; occupancy
//     (6..16), edges/thread (1..4), PDL, and kernel fusion are all neutral.
//   - pack: (x,s)->float4 table makes every edge gather exactly 1 sector/endpoint.
//   - node: scalar grid, fused finalize via last-block counter.
// (R14 bench was an infra failure — Trio nursery exception before execution;
//  this source is byte-identical to the config that passed twice at ~61.4us.)
// ---------------------------------------------------------------------------

#define NMAX 100000

__device__ float4 g_P[NMAX];        // (x0,x1,x2,s)
__device__ float4 g_Z[NMAX];        // accumulator (w unused)
__device__ double g_acc[3];         // sum(1-|cos|), sum(ang_deg), count
__device__ unsigned int g_done;     // last-block-done counter

// ---------------------------------------------------------------------------
// Scalar pack: warp-coalesced loads, aligned 16B stores. grid ~391.
__global__ void pack_kernel(const float* __restrict__ x,
                            const float* __restrict__ s,
                            int N) {
    int i = blockIdx.x * blockDim.x + threadIdx.x;
    if (i < N) {
        g_P[i] = make_float4(x[3 * i], x[3 * i + 1], x[3 * i + 2], s[i]);
        g_Z[i] = make_float4(0.f, 0.f, 0.f, 0.f);
    }
    if (i == 0) {
        g_acc[0] = 0.0; g_acc[1] = 0.0; g_acc[2] = 0.0;
        g_done = 0u;
    }
}

// ---------------------------------------------------------------------------
// 1 edge/thread, occ 16 (2048 threads/SM). LTS-RMW-bound; best measured.
__global__ __launch_bounds__(128, 16)
void edge_kernel(const int* __restrict__ ei, int E) {
    int e = blockIdx.x * blockDim.x + threadIdx.x;
    if (e >= E) return;

    int a = __ldg(ei + e);
    int b = __ldg(ei + E + e);

    float4 Pa = __ldg(&g_P[a]);
    float4 Pb = __ldg(&g_P[b]);

    float ds = Pb.w - Pa.w;
    float cx = (Pb.x - Pa.x) * ds;
    float cy = (Pb.y - Pa.y) * ds;
    float cz = (Pb.z - Pa.z) * ds;

    asm volatile("red.global.add.v4.f32 [%0], {%1, %2, %3, %4};"
                 :: "l"((float*)&g_Z[a]), "f"(cx), "f"(cy), "f"(cz), "f"(0.0f) : "memory");
    asm volatile("red.global.add.v4.f32 [%0], {%1, %2, %3, %4};"
                 :: "l"((float*)&g_Z[b]), "f"(cx), "f"(cy), "f"(cz), "f"(0.0f) : "memory");
}

// ---------------------------------------------------------------------------
// Scalar node reduction (1 node/thread, TB=512 -> grid ~196) + fused finalize.
__global__ void node_kernel(const float* __restrict__ y,
                            const int* __restrict__ mask,
                            int N, float* __restrict__ out) {
    int i = blockIdx.x * blockDim.x + threadIdx.x;

    float l = 0.f, ang = 0.f, c = 0.f;
    if (i < N && mask[i] != 0) {
        float4 Z = g_Z[i];
        float y0 = y[3 * i], y1 = y[3 * i + 1], y2 = y[3 * i + 2];
        float dot = y0 * Z.x + y1 * Z.y + y2 * Z.z;
        float nz = sqrtf(Z.x * Z.x + Z.y * Z.y + Z.z * Z.z);
        float ny = sqrtf(y0 * y0 + y1 * y1 + y2 * y2);
        float cosv = dot / (ny * nz);
        l = 1.0f - fabsf(cosv);
        float cl = fminf(1.0f, fmaxf(-1.0f, cosv));
        ang = acosf(cl) * 57.295779513082320877f;  // degrees
        c = 1.0f;
    }

    #pragma unroll
    for (int o = 16; o > 0; o >>= 1) {
        l   += __shfl_down_sync(0xffffffffu, l,   o);
        ang += __shfl_down_sync(0xffffffffu, ang, o);
        c   += __shfl_down_sync(0xffffffffu, c,   o);
    }

    __shared__ float sl[16], sa_[16], sc[16];
    __shared__ bool is_last;
    int wid = threadIdx.x >> 5;
    int lid = threadIdx.x & 31;
    if (lid == 0) { sl[wid] = l; sa_[wid] = ang; sc[wid] = c; }
    __syncthreads();

    if (threadIdx.x == 0) {
        float bl = 0.f, ba = 0.f, bc = 0.f;
        int nwarp = (blockDim.x + 31) >> 5;
        for (int w = 0; w < nwarp; w++) { bl += sl[w]; ba += sa_[w]; bc += sc[w]; }
        atomicAdd(&g_acc[0], (double)bl);
        atomicAdd(&g_acc[1], (double)ba);
        atomicAdd(&g_acc[2], (double)bc);
        __threadfence();
        unsigned int done = atomicAdd(&g_done, 1u);
        is_last = (done == gridDim.x - 1);
    }
    __syncthreads();

    if (is_last && threadIdx.x == 0) {
        double cnt = g_acc[2];
        if (cnt < 1.0) cnt = 1.0;
        out[0] = (float)(g_acc[0] / cnt);
        out[1] = (float)(g_acc[1] / cnt);
    }
}

// ---------------------------------------------------------------------------
extern "C" void kernel_launch(void* const* d_in, const int* in_sizes, int n_in,
                              void* d_out, int out_size) {
    const float* x    = (const float*)d_in[0];   // [N,3]
    const float* y    = (const float*)d_in[1];   // [N,3]
    const float* s    = (const float*)d_in[2];   // [N]
    const int*   ei   = (const int*)d_in[3];     // [2,E] int32 (canonicalized int64)
    const int*   mask = (const int*)d_in[4];     // [N]   int32 (canonicalized bool)
    float* out = (float*)d_out;

    int N = in_sizes[2];
    int E = in_sizes[3] / 2;

    const int TBP = 256;                              // pack: grid ~391
    pack_kernel<<<(N + TBP - 1) / TBP, TBP>>>(x, s, N);

    const int TBE = 128;                              // edge: grid 25000
    edge_kernel<<<(E + TBE - 1) / TBE, TBE>>>(ei, E);

    const int TBN = 512;                              // node: grid ~196
    node_kernel<<<(N + TBN - 1) / TBN, TBN>>>(y, mask, N, out);
}

// round 17
// speedup vs baseline: 1.0005x; 1.0005x over previous
#include <cuda_runtime.h>
#include <cstdint>

// ---------------------------------------------------------------------------
// CustomOrientationLoss — FINAL (locked; measured 61.44/61.47/61.47us).
//
//   Z[v] = sum_{(u,v) in E} (x[u]-x[v])*(s[u]-s[v])   [symmetric per edge:
//          computed once, RED-scattered to both endpoints]
//   cos  = <y,Z>/(|y||Z|);  out = { mean(1-|cos|), mean(deg(acos cos)) }
//
// Performance structure (established R4-R15):
//   - edge phase (~52us) sits AT the LTS sector-RMW roofline:
//       6.4M gather sectors + 6.4M RMW sectors ~= (1+2)cyc/slice model.
//     2 RMW sectors/edge is minimal for any scatter formulation; occupancy
//     (6..16), edges/thread (1..4), PDL, fusion, bf16 packing, v2 splits,
//     streaming hints, warp dedup: all neutral or negative by model/measure.
//   - pack: (x,s)->float4 table makes every edge gather exactly 1 sector/endpoint.
//   - node: scalar grid, fused finalize via last-block counter.
// (R16 bench was an infra failure — container failed before execution; this
//  source is byte-identical to the config that passed 3x at ~61.4us.)
// ---------------------------------------------------------------------------

#define NMAX 100000

__device__ float4 g_P[NMAX];        // (x0,x1,x2,s)
__device__ float4 g_Z[NMAX];        // accumulator (w unused)
__device__ double g_acc[3];         // sum(1-|cos|), sum(ang_deg), count
__device__ unsigned int g_done;     // last-block-done counter

// ---------------------------------------------------------------------------
// Scalar pack: warp-coalesced loads, aligned 16B stores. grid ~391.
__global__ void pack_kernel(const float* __restrict__ x,
                            const float* __restrict__ s,
                            int N) {
    int i = blockIdx.x * blockDim.x + threadIdx.x;
    if (i < N) {
        g_P[i] = make_float4(x[3 * i], x[3 * i + 1], x[3 * i + 2], s[i]);
        g_Z[i] = make_float4(0.f, 0.f, 0.f, 0.f);
    }
    if (i == 0) {
        g_acc[0] = 0.0; g_acc[1] = 0.0; g_acc[2] = 0.0;
        g_done = 0u;
    }
}

// ---------------------------------------------------------------------------
// 1 edge/thread, occ 16 (2048 threads/SM). LTS-RMW-bound; best measured.
__global__ __launch_bounds__(128, 16)
void edge_kernel(const int* __restrict__ ei, int E) {
    int e = blockIdx.x * blockDim.x + threadIdx.x;
    if (e >= E) return;

    int a = __ldg(ei + e);
    int b = __ldg(ei + E + e);

    float4 Pa = __ldg(&g_P[a]);
    float4 Pb = __ldg(&g_P[b]);

    float ds = Pb.w - Pa.w;
    float cx = (Pb.x - Pa.x) * ds;
    float cy = (Pb.y - Pa.y) * ds;
    float cz = (Pb.z - Pa.z) * ds;

    asm volatile("red.global.add.v4.f32 [%0], {%1, %2, %3, %4};"
                 :: "l"((float*)&g_Z[a]), "f"(cx), "f"(cy), "f"(cz), "f"(0.0f) : "memory");
    asm volatile("red.global.add.v4.f32 [%0], {%1, %2, %3, %4};"
                 :: "l"((float*)&g_Z[b]), "f"(cx), "f"(cy), "f"(cz), "f"(0.0f) : "memory");
}

// ---------------------------------------------------------------------------
// Scalar node reduction (1 node/thread, TB=512 -> grid ~196) + fused finalize.
__global__ void node_kernel(const float* __restrict__ y,
                            const int* __restrict__ mask,
                            int N, float* __restrict__ out) {
    int i = blockIdx.x * blockDim.x + threadIdx.x;

    float l = 0.f, ang = 0.f, c = 0.f;
    if (i < N && mask[i] != 0) {
        float4 Z = g_Z[i];
        float y0 = y[3 * i], y1 = y[3 * i + 1], y2 = y[3 * i + 2];
        float dot = y0 * Z.x + y1 * Z.y + y2 * Z.z;
        float nz = sqrtf(Z.x * Z.x + Z.y * Z.y + Z.z * Z.z);
        float ny = sqrtf(y0 * y0 + y1 * y1 + y2 * y2);
        float cosv = dot / (ny * nz);
        l = 1.0f - fabsf(cosv);
        float cl = fminf(1.0f, fmaxf(-1.0f, cosv));
        ang = acosf(cl) * 57.295779513082320877f;  // degrees
        c = 1.0f;
    }

    #pragma unroll
    for (int o = 16; o > 0; o >>= 1) {
        l   += __shfl_down_sync(0xffffffffu, l,   o);
        ang += __shfl_down_sync(0xffffffffu, ang, o);
        c   += __shfl_down_sync(0xffffffffu, c,   o);
    }

    __shared__ float sl[16], sa_[16], sc[16];
    __shared__ bool is_last;
    int wid = threadIdx.x >> 5;
    int lid = threadIdx.x & 31;
    if (lid == 0) { sl[wid] = l; sa_[wid] = ang; sc[wid] = c; }
    __syncthreads();

    if (threadIdx.x == 0) {
        float bl = 0.f, ba = 0.f, bc = 0.f;
        int nwarp = (blockDim.x + 31) >> 5;
        for (int w = 0; w < nwarp; w++) { bl += sl[w]; ba += sa_[w]; bc += sc[w]; }
        atomicAdd(&g_acc[0], (double)bl);
        atomicAdd(&g_acc[1], (double)ba);
        atomicAdd(&g_acc[2], (double)bc);
        __threadfence();
        unsigned int done = atomicAdd(&g_done, 1u);
        is_last = (done == gridDim.x - 1);
    }
    __syncthreads();

    if (is_last && threadIdx.x == 0) {
        double cnt = g_acc[2];
        if (cnt < 1.0) cnt = 1.0;
        out[0] = (float)(g_acc[0] / cnt);
        out[1] = (float)(g_acc[1] / cnt);
    }
}

// ---------------------------------------------------------------------------
extern "C" void kernel_launch(void* const* d_in, const int* in_sizes, int n_in,
                              void* d_out, int out_size) {
    const float* x    = (const float*)d_in[0];   // [N,3]
    const float* y    = (const float*)d_in[1];   // [N,3]
    const float* s    = (const float*)d_in[2];   // [N]
    const int*   ei   = (const int*)d_in[3];     // [2,E] int32 (canonicalized int64)
    const int*   mask = (const int*)d_in[4];     // [N]   int32 (canonicalized bool)
    float* out = (float*)d_out;

    int N = in_sizes[2];
    int E = in_sizes[3] / 2;

    const int TBP = 256;                              // pack: grid ~391
    pack_kernel<<<(N + TBP - 1) / TBP, TBP>>>(x, s, N);

    const int TBE = 128;                              // edge: grid 25000
    edge_kernel<<<(E + TBE - 1) / TBE, TBE>>>(ei, E);

    const int TBN = 512;                              // node: grid ~196
    node_kernel<<<(N + TBN - 1) / TBN, TBN>>>(y, mask, N, out);
}